// round 3
// baseline (speedup 1.0000x reference)
#include <cuda_runtime.h>
#include <cstdint>

#define N_      2048
#define T_      512
#define B_      32
#define NCTA    128
#define NLOC    16          // neurons per CTA
#define NTHR    512
#define CJ      256         // A j-chunk size
#define NCHUNK  (N_ / CJ)   // 8

#define JPAD    2052        // J smem row stride (floats), 16B-aligned, bank-spread
#define APAD    260         // A chunk smem row stride (floats), 16B-aligned

#define DT_     1e-4f
#define U_C     0.3f
#define TAU_    0.008f
#define TAU_F   1.5f
#define TAU_D   0.3f
#define ALPHA_  1.5f
#define I_B_    8.0f
#define J_EI_   1.1f
#define J_IE_   2.2f

// output layout: tuple (all_h, all_u, all_x, all_hI, outputs) concatenated
#define OFF_H   ((size_t)0)
#define OFF_U   ((size_t)T_ * B_ * N_)
#define OFF_X   ((size_t)2 * T_ * B_ * N_)
#define OFF_HI  ((size_t)3 * T_ * B_ * N_)
#define OFF_OUT (OFF_HI + (size_t)T_ * B_)

// ---- static device scratch (no allocation) ----
__device__ float g_A[2][N_ * B_];        // activation u*x*R, [j][b], double buffered
__device__ float g_pR[2][NCTA * B_];     // per-CTA partial sum R, [cta][b]
__device__ float g_pO[2][NCTA * B_];     // per-CTA partial sum R*W_out, [cta][b]
__device__ unsigned int g_bar  = 0;      // monotonic grid barrier counter
__device__ unsigned int g_exit = 0;      // exit counter (resets g_bar for graph replays)

// R(h) = ALPHA * softplus(h/ALPHA), numerically stable
__device__ __forceinline__ float rate_fn(float h) {
    float z  = h * (1.0f / ALPHA_);
    float sp = fmaxf(z, 0.0f) + log1pf(__expf(-fabsf(z)));
    return ALPHA_ * sp;
}

__device__ __forceinline__ void grid_bar(unsigned int target) {
    __syncthreads();
    if (threadIdx.x == 0) {
        __threadfence();
        atomicAdd(&g_bar, 1u);
        while (*(volatile unsigned int*)&g_bar < target) { }
        __threadfence();
    }
    __syncthreads();
}

// smem float offsets
#define SM_J    0
#define SM_A    (NLOC * JPAD)              // 32832
#define SM_SUM  (SM_A + 32 * APAD)         // +8320 = 41152
#define SMEM_FLOATS (SM_SUM + 32)          // 41184
#define SMEM_BYTES  (SMEM_FLOATS * 4)      // 164736

__global__ void __launch_bounds__(NTHR, 1)
stp_kernel(const float* __restrict__ inp,    // [T,B,1]
           const float* __restrict__ W_in,   // [N,1]
           const float* __restrict__ J,      // [N,N]
           const float* __restrict__ W_out,  // [1,N]
           float* __restrict__ out)
{
    extern __shared__ float sm[];
    float* Jsm  = sm + SM_J;     // [il][j] padded rows
    float* As   = sm + SM_A;     // [b][jj] padded rows (current A chunk)
    float* sSum = sm + SM_SUM;   // [b] total sum of R

    const int tid  = threadIdx.x;
    const int cta  = blockIdx.x;
    const int il   = tid & 15;          // local neuron 0..15
    const int b    = tid >> 4;          // batch 0..31
    const int i    = cta * NLOC + il;   // global neuron
    const int lane = tid & 31;
    const int warp = tid >> 5;

    // stage thread mapping for A chunks
    const int sb = tid & 31;            // batch column
    const int sj = tid >> 5;            // j row base (0..15), elements sj+16k

    // ---- load this CTA's 16 J rows into smem (once) ----
    {
        const float4* J4 = (const float4*)(J + (size_t)cta * NLOC * N_);
        for (int k = tid; k < NLOC * (N_ / 4); k += NTHR) {
            int r = k >> 9;             // / (N_/4)
            int c = k & 511;            // % (N_/4)
            float4 v = __ldg(&J4[r * (N_ / 4) + c]);
            *(float4*)&Jsm[r * JPAD + 4 * c] = v;
        }
    }

    // ---- init state (registers) ----
    float h = 0.0f, u = U_C, x = 1.0f, hI = 0.0f;
    const float wi = __ldg(&W_in[i]);
    const float wo = __ldg(&W_out[i]);

    // ---- publish A0, pR0 into buffer 0 ----
    float Rcur = rate_fn(h);
    {
        float A0 = u * x * Rcur;
        __stcg(&g_A[0][(size_t)i * B_ + b], A0);
        float s = Rcur;
        #pragma unroll
        for (int o = 8; o > 0; o >>= 1) s += __shfl_xor_sync(0xffffffffu, s, o);
        if (il == 0) __stcg(&g_pR[0][cta * B_ + b], s);
    }
    __syncthreads();
    grid_bar(NCTA * 1u);

    for (int t = 0; t < T_; ++t) {
        const int buf  = t & 1;
        const int nbuf = buf ^ 1;

        // --- warp 0: reduce total sum of R across CTAs into sSum ---
        if (warp == 0) {
            float s = 0.0f;
            for (int c = 0; c < NCTA; ++c)
                s += __ldcg(&g_pR[buf][c * B_ + lane]);
            sSum[lane] = s;
        }
        // --- CTA 0 warp 1: reduce output partials, write outputs[t-1] ---
        if (cta == 0 && warp == 1 && t > 0) {
            float s = 0.0f;
            for (int c = 0; c < NCTA; ++c)
                s += __ldcg(&g_pO[buf][c * B_ + lane]);
            out[OFF_OUT + (size_t)(t - 1) * B_ + lane] = s;
        }

        // --- matmul: acc = sum_j A[b][j] * J[i][j], A chunked through smem ---
        float acc = 0.0f;
        float r0[16];
        #pragma unroll
        for (int k = 0; k < 16; ++k)
            r0[k] = __ldcg(&g_A[buf][(size_t)(sj + 16 * k) * B_ + sb]);

        for (int c = 0; c < NCHUNK; ++c) {
            __syncthreads();   // As free; (first iter: also fences sSum)
            #pragma unroll
            for (int k = 0; k < 16; ++k)
                As[sb * APAD + sj + 16 * k] = r0[k];
            __syncthreads();   // As ready
            if (c + 1 < NCHUNK) {
                const int j0n = (c + 1) * CJ;
                #pragma unroll
                for (int k = 0; k < 16; ++k)
                    r0[k] = __ldcg(&g_A[buf][(size_t)(j0n + sj + 16 * k) * B_ + sb]);
            }
            const float4* a4 = (const float4*)&As[b * APAD];
            const float4* j4 = (const float4*)&Jsm[il * JPAD + c * CJ];
            #pragma unroll
            for (int q = 0; q < CJ / 4; ++q) {
                float4 av = a4[q];
                float4 jv = j4[q];
                acc = fmaf(av.x, jv.x, acc);
                acc = fmaf(av.y, jv.y, acc);
                acc = fmaf(av.z, jv.z, acc);
                acc = fmaf(av.w, jv.w, acc);
            }
        }

        // --- state update ---
        float sumR = sSum[b];
        float Ie   = __ldg(&inp[t * B_ + b]) * wi;
        float RI   = rate_fn(hI);
        float dh   = (-h + acc + I_B_ + Ie) * (1.0f / TAU_) - J_EI_ * RI * (1.0f / TAU_);
        float du   = (U_C - u) * (1.0f / TAU_F) + U_C * (1.0f - u) * Rcur;
        float dx   = (1.0f - x) * (1.0f / TAU_D) - u * x * Rcur;
        float dhI  = (-hI + J_IE_ * sumR) * (1.0f / TAU_);
        h  += dh  * DT_;
        u  += du  * DT_;
        x  += dx  * DT_;
        hI += dhI * DT_;

        // --- write state outputs ---
        const size_t row = (size_t)(t * B_ + b) * N_ + i;
        __stcs(&out[OFF_H + row], h);
        __stcs(&out[OFF_U + row], u);
        __stcs(&out[OFF_X + row], x);
        if (cta == 0 && il == 0)
            out[OFF_HI + (size_t)t * B_ + b] = hI;

        // --- publish next-step activation + partials ---
        Rcur = rate_fn(h);
        {
            float A2 = u * x * Rcur;
            __stcg(&g_A[nbuf][(size_t)i * B_ + b], A2);
            float sR = Rcur;
            float sO = Rcur * wo;
            #pragma unroll
            for (int o = 8; o > 0; o >>= 1) {
                sR += __shfl_xor_sync(0xffffffffu, sR, o);
                sO += __shfl_xor_sync(0xffffffffu, sO, o);
            }
            if (il == 0) {
                __stcg(&g_pR[nbuf][cta * B_ + b], sR);
                __stcg(&g_pO[nbuf][cta * B_ + b], sO);
            }
        }
        grid_bar((unsigned)NCTA * (unsigned)(t + 2));
    }

    // final output row: outputs[T-1] from buffer T_&1 (== 0)
    if (cta == 0 && warp == 0) {
        float s = 0.0f;
        for (int c = 0; c < NCTA; ++c)
            s += __ldcg(&g_pO[T_ & 1][c * B_ + lane]);
        out[OFF_OUT + (size_t)(T_ - 1) * B_ + lane] = s;
    }

    // ---- reset barrier counters so CUDA-graph replays start clean ----
    __syncthreads();
    if (tid == 0) {
        __threadfence();
        unsigned int v = atomicAdd(&g_exit, 1u);
        if (v == NCTA - 1) {
            g_bar  = 0;
            g_exit = 0;
            __threadfence();
        }
    }
}

extern "C" void kernel_launch(void* const* d_in, const int* in_sizes, int n_in,
                              void* d_out, int out_size) {
    const float* inp   = (const float*)d_in[0];
    const float* W_in  = (const float*)d_in[1];
    const float* J     = (const float*)d_in[2];
    const float* W_out = (const float*)d_in[3];
    float* out = (float*)d_out;

    static bool attr_done = false;
    if (!attr_done) {
        cudaFuncSetAttribute(stp_kernel,
                             cudaFuncAttributeMaxDynamicSharedMemorySize,
                             SMEM_BYTES);
        attr_done = true;
    }
    stp_kernel<<<NCTA, NTHR, SMEM_BYTES>>>(inp, W_in, J, W_out, out);
}

// round 4
// speedup vs baseline: 3.4435x; 3.4435x over previous
#include <cuda_runtime.h>
#include <cstdint>

#define N_      2048
#define T_      512
#define B_      32
#define NCTA    128
#define NLOC    16          // neurons per CTA
#define NTHR    512
#define CJ      256         // A j-chunk size
#define NCHUNK  8
#define ROWPAD  36          // floats per A row in smem (144 B, 16B-aligned, bank-skewed)

#define DT_     1e-4f
#define U_C     0.3f
#define TAU_    0.008f
#define TAU_F   1.5f
#define TAU_D   0.3f
#define ALPHA_  1.5f
#define I_B_    8.0f
#define J_EI_   1.1f
#define J_IE_   2.2f

// output layout: tuple (all_h, all_u, all_x, all_hI, outputs) concatenated
#define OFF_H   ((size_t)0)
#define OFF_U   ((size_t)T_ * B_ * N_)
#define OFF_X   ((size_t)2 * T_ * B_ * N_)
#define OFF_HI  ((size_t)3 * T_ * B_ * N_)
#define OFF_OUT (OFF_HI + (size_t)T_ * B_)

// ---- static device scratch (no allocation) ----
__device__ float g_A[2][N_ * B_];        // activation u*x*R, [j][b], double buffered
__device__ float g_pR[2][NCTA * B_];     // per-CTA partial sum R, [cta][b]
__device__ float g_pO[2][NCTA * B_];     // per-CTA partial sum R*W_out, [cta][b]
__device__ unsigned int g_bar  = 0;      // monotonic grid barrier counter
__device__ unsigned int g_exit = 0;      // exit counter (resets g_bar for graph replays)

// smem float offsets
#define SM_AS    0                        // [2][CJ][ROWPAD]  double-buffered A chunk
#define AS_CH    (CJ * ROWPAD)            // 9216 floats per buffer
#define SM_PART  (2 * AS_CH)              // 18432 : partial sums [256 rows][ROWPAD]
#define SM_SG    (SM_PART + CJ * ROWPAD)  // 27648 : warp partial sumR [16][33]
#define SMEM_FLOATS (SM_SG + 16 * 33 + 32)
#define SMEM_BYTES  (SMEM_FLOATS * 4)     // ~113 KB

// R(h) = ALPHA * softplus(h/ALPHA), numerically stable
__device__ __forceinline__ float rate_fn(float h) {
    float z  = h * (1.0f / ALPHA_);
    float sp = fmaxf(z, 0.0f) + log1pf(__expf(-fabsf(z)));
    return ALPHA_ * sp;
}

__device__ __forceinline__ void grid_bar(unsigned int target) {
    __syncthreads();
    if (threadIdx.x == 0) {
        __threadfence();
        atomicAdd(&g_bar, 1u);
        while (*(volatile unsigned int*)&g_bar < target) { }
        __threadfence();
    }
    __syncthreads();
}

// ---- packed f32x2 helpers (Blackwell) ----
__device__ __forceinline__ unsigned long long pack2(float v) {
    unsigned long long r;
    asm("mov.b64 %0, {%1, %1};" : "=l"(r) : "f"(v));
    return r;
}
__device__ __forceinline__ void fma2(unsigned long long& d,
                                     unsigned long long a,
                                     unsigned long long b) {
    asm("fma.rn.f32x2 %0, %1, %2, %0;" : "+l"(d) : "l"(a), "l"(b));
}
__device__ __forceinline__ unsigned long long add2(unsigned long long a,
                                                   unsigned long long b) {
    unsigned long long r;
    asm("add.rn.f32x2 %0, %1, %2;" : "=l"(r) : "l"(a), "l"(b));
    return r;
}

// ---- cp.async helpers ----
__device__ __forceinline__ void cp_async16(uint32_t smem_addr, const void* gptr) {
    asm volatile("cp.async.cg.shared.global [%0], [%1], 16;"
                 :: "r"(smem_addr), "l"(gptr));
}
__device__ __forceinline__ void cp_commit() {
    asm volatile("cp.async.commit_group;");
}
template <int NKeep>
__device__ __forceinline__ void cp_wait() {
    asm volatile("cp.async.wait_group %0;" :: "n"(NKeep));
}

__global__ void __launch_bounds__(NTHR, 1)
stp_kernel(const float* __restrict__ inp,    // [T,B,1]
           const float* __restrict__ W_in,   // [N,1]
           const float* __restrict__ J,      // [N,N]
           const float* __restrict__ W_out,  // [1,N]
           float* __restrict__ out)
{
    extern __shared__ float sm[];
    float* As   = sm + SM_AS;     // [2][256][36]
    float* part = sm + SM_PART;   // [256][36]
    float* sG   = sm + SM_SG;     // [16][33]

    const int tid  = threadIdx.x;
    const int cta  = blockIdx.x;
    const int il   = tid & 15;          // local neuron 0..15 (matmul AND state role)
    const int s    = tid >> 4;          // j-slice 0..31 (matmul) == batch b (state)
    const int b    = s;
    const int lane = tid & 31;
    const int warp = tid >> 5;
    const int i    = cta * NLOC + il;   // global neuron

    const uint32_t as_base = (uint32_t)__cvta_generic_to_shared(As);

    // ---- load this thread's 64 J coefficients into registers ----
    float Jreg[64];
    {
        const float* Jrow = J + (size_t)i * N_;
        #pragma unroll
        for (int c = 0; c < 8; ++c)
            #pragma unroll
            for (int q = 0; q < 8; ++q)
                Jreg[c * 8 + q] = __ldg(&Jrow[c * CJ + q * 32 + s]);
    }

    // ---- init state (registers) ----
    float h = 0.0f, u = U_C, x = 1.0f, hI = 0.0f;
    const float wi = __ldg(&W_in[i]);
    const float wo = __ldg(&W_out[i]);

    // ---- publish A0, pR0 into buffer 0 ----
    float Rcur = rate_fn(h);
    {
        float A0 = u * x * Rcur;
        __stcg(&g_A[0][(size_t)i * B_ + b], A0);
        float sR = Rcur;
        #pragma unroll
        for (int o = 8; o > 0; o >>= 1) sR += __shfl_xor_sync(0xffffffffu, sR, o);
        if (il == 0) __stcg(&g_pR[0][cta * B_ + b], sR);
    }
    __syncthreads();
    grid_bar(NCTA * 1u);

    for (int t = 0; t < T_; ++t) {
        const int buf  = t & 1;
        const int nbuf = buf ^ 1;
        const float* gA = g_A[buf];

        // --- prologue: cp.async chunk 0 into As buffer 0 ---
        {
            #pragma unroll
            for (int o = 0; o < 4; ++o) {
                int n = o * NTHR + tid;
                int r = n >> 3, seg = n & 7;
                cp_async16(as_base + (uint32_t)((r * ROWPAD + seg * 4) << 2),
                           gA + (size_t)r * B_ + seg * 4);
            }
            cp_commit();
        }

        // --- each warp reduces 8 CTAs' R-partials (overlaps cp.async latency) ---
        {
            float sum = 0.0f;
            #pragma unroll
            for (int k = 0; k < 8; ++k)
                sum += __ldcg(&g_pR[buf][(warp * 8 + k) * B_ + lane]);
            sG[warp * 33 + lane] = sum;
        }
        // --- CTA 0 warp 1: reduce output partials, write outputs[t-1] ---
        if (cta == 0 && warp == 1 && t > 0) {
            float sum = 0.0f;
            for (int c = 0; c < NCTA; ++c)
                sum += __ldcg(&g_pO[buf][c * B_ + lane]);
            out[OFF_OUT + (size_t)(t - 1) * B_ + lane] = sum;
        }

        // --- matmul: acc2[m] = sum_{this thread's j} J[i][j] * A[j][2m..2m+1] ---
        unsigned long long acc2[16];
        #pragma unroll
        for (int m = 0; m < 16; ++m) acc2[m] = 0ull;

        #pragma unroll
        for (int c = 0; c < NCHUNK; ++c) {
            if (c + 1 < NCHUNK) {
                const int abuf = (c + 1) & 1;
                #pragma unroll
                for (int o = 0; o < 4; ++o) {
                    int n = o * NTHR + tid;
                    int r = n >> 3, seg = n & 7;
                    cp_async16(as_base + (uint32_t)((abuf * AS_CH + r * ROWPAD + seg * 4) << 2),
                               gA + (size_t)((c + 1) * CJ + r) * B_ + seg * 4);
                }
                cp_commit();
                cp_wait<1>();
            } else {
                cp_wait<0>();
            }
            __syncthreads();   // chunk c visible to all threads

            const float* Ab = As + (c & 1) * AS_CH;
            #pragma unroll
            for (int q = 0; q < 8; ++q) {
                const int r = q * 32 + s;
                const ulonglong2* a8 = (const ulonglong2*)(Ab + r * ROWPAD);
                unsigned long long jp = pack2(Jreg[c * 8 + q]);
                #pragma unroll
                for (int e = 0; e < 8; ++e) {
                    ulonglong2 v = a8[e];
                    fma2(acc2[2 * e],     v.x, jp);
                    fma2(acc2[2 * e + 1], v.y, jp);
                }
            }
            __syncthreads();   // all reads of buffer (c&1) done before overwrite
        }

        // --- reduce partials: pair s with s^1 via shfl, dump 16 k-slices to smem ---
        #pragma unroll
        for (int m = 0; m < 16; ++m) {
            unsigned long long o = __shfl_xor_sync(0xffffffffu, acc2[m], 16);
            acc2[m] = add2(acc2[m], o);
        }
        if ((lane & 16) == 0) {           // s even; k = s>>1 == warp
            unsigned long long* dst = (unsigned long long*)(part + (warp * 16 + il) * ROWPAD);
            #pragma unroll
            for (int m = 0; m < 16; ++m) dst[m] = acc2[m];
        }
        __syncthreads();

        // --- final sums: thread (il, b) gathers its output ---
        float syn = 0.0f;
        #pragma unroll
        for (int k = 0; k < 16; ++k)
            syn += part[(k * 16 + il) * ROWPAD + b];
        float sumR = 0.0f;
        #pragma unroll
        for (int w = 0; w < 16; ++w)
            sumR += sG[w * 33 + b];

        // --- state update ---
        float Ie  = __ldg(&inp[t * B_ + b]) * wi;
        float RI  = rate_fn(hI);
        float dh  = (-h + syn + I_B_ + Ie) * (1.0f / TAU_) - J_EI_ * RI * (1.0f / TAU_);
        float du  = (U_C - u) * (1.0f / TAU_F) + U_C * (1.0f - u) * Rcur;
        float dx  = (1.0f - x) * (1.0f / TAU_D) - u * x * Rcur;
        float dhI = (-hI + J_IE_ * sumR) * (1.0f / TAU_);
        h  += dh  * DT_;
        u  += du  * DT_;
        x  += dx  * DT_;
        hI += dhI * DT_;

        // --- write state outputs (16 il consecutive -> 64B runs) ---
        const size_t row = (size_t)(t * B_ + b) * N_ + i;
        __stcs(&out[OFF_H + row], h);
        __stcs(&out[OFF_U + row], u);
        __stcs(&out[OFF_X + row], x);
        if (cta == 0 && il == 0)
            out[OFF_HI + (size_t)t * B_ + b] = hI;

        // --- publish next-step activation + partials ---
        Rcur = rate_fn(h);
        {
            float A2 = u * x * Rcur;
            __stcg(&g_A[nbuf][(size_t)i * B_ + b], A2);
            float sR = Rcur;
            float sO = Rcur * wo;
            #pragma unroll
            for (int o = 8; o > 0; o >>= 1) {
                sR += __shfl_xor_sync(0xffffffffu, sR, o);
                sO += __shfl_xor_sync(0xffffffffu, sO, o);
            }
            if (il == 0) {
                __stcg(&g_pR[nbuf][cta * B_ + b], sR);
                __stcg(&g_pO[nbuf][cta * B_ + b], sO);
            }
        }
        grid_bar((unsigned)NCTA * (unsigned)(t + 2));
    }

    // final output row: outputs[T-1] from buffer (T_)&1 == 0
    if (cta == 0 && warp == 0) {
        float sum = 0.0f;
        for (int c = 0; c < NCTA; ++c)
            sum += __ldcg(&g_pO[T_ & 1][c * B_ + lane]);
        out[OFF_OUT + (size_t)(T_ - 1) * B_ + lane] = sum;
    }

    // ---- reset barrier counters so CUDA-graph replays start clean ----
    __syncthreads();
    if (tid == 0) {
        __threadfence();
        unsigned int v = atomicAdd(&g_exit, 1u);
        if (v == NCTA - 1) {
            g_bar  = 0;
            g_exit = 0;
            __threadfence();
        }
    }
}

extern "C" void kernel_launch(void* const* d_in, const int* in_sizes, int n_in,
                              void* d_out, int out_size) {
    const float* inp   = (const float*)d_in[0];
    const float* W_in  = (const float*)d_in[1];
    const float* J     = (const float*)d_in[2];
    const float* W_out = (const float*)d_in[3];
    float* out = (float*)d_out;

    static bool attr_done = false;
    if (!attr_done) {
        cudaFuncSetAttribute(stp_kernel,
                             cudaFuncAttributeMaxDynamicSharedMemorySize,
                             SMEM_BYTES);
        attr_done = true;
    }
    stp_kernel<<<NCTA, NTHR, SMEM_BYTES>>>(inp, W_in, J, W_out, out);
}